// round 15
// baseline (speedup 1.0000x reference)
#include <cuda_runtime.h>

typedef unsigned long long ull;

// Problem constants
#define B_  32
#define IC_ 1152
#define OC_ 10
#define ID_ 8
#define OD_ 16
#define N_ITER_ 5
#define EPS_ 1e-20f

#define GI_    8                  // ic's per CTA
#define NBLK_  ((IC_ / GI_) * 2)  // 288 CTAs: 144 ic-groups x 2 batch-halves
#define NTHR_  320                // 10 warps: warp = oc, lane = (b_lo, h)
#define WPC_   (OC_ * ID_ * OD_)  // 1280 floats of weights per ic
#define EH_    (OD_ / 2)          // 8 e's per thread
#define EP_    (EH_ / 2)          // 4 packed f32x2 per thread

__device__ __forceinline__ float frcp(float a) {
    float r;
    asm("rcp.approx.f32 %0, %1;" : "=f"(r) : "f"(a));
    return r;
}

// Packed fp32x2 ops (sm_103a; only reachable via PTX)
__device__ __forceinline__ ull FMA2(ull a, ull b, ull c) {
    ull d;
    asm("fma.rn.f32x2 %0, %1, %2, %3;" : "=l"(d) : "l"(a), "l"(b), "l"(c));
    return d;
}
__device__ __forceinline__ ull MUL2(ull a, ull b) {
    ull d;
    asm("mul.rn.f32x2 %0, %1, %2;" : "=l"(d) : "l"(a), "l"(b));
    return d;
}
__device__ __forceinline__ ull ADD2(ull a, ull b) {
    ull d;
    asm("add.rn.f32x2 %0, %1, %2;" : "=l"(d) : "l"(a), "l"(b));
    return d;
}

// Pack/unpack through register-pair aliasing (no mov.b64 round trips)
union f2u { ull u; float2 f; };
__device__ __forceinline__ ull PACK2(float lo, float hi) {
    f2u x; x.f.x = lo; x.f.y = hi; return x.u;
}
__device__ __forceinline__ float SUM2(ull v) {
    f2u x; x.u = v; return x.f.x + x.f.y;
}
__device__ __forceinline__ float LO2(ull v) { f2u x; x.u = v; return x.f.x; }
__device__ __forceinline__ float HI2(ull v) { f2u x; x.u = v; return x.f.y; }

__device__ __forceinline__ unsigned smaddr(const void* p) {
    return (unsigned)__cvta_generic_to_shared(p);
}
#define CP16(dst_u32, src_ptr) \
    asm volatile("cp.async.cg.shared.global [%0], [%1], 16;" \
                 :: "r"(dst_u32), "l"(src_ptr) : "memory")
#define CP_COMMIT()  asm volatile("cp.async.commit_group;" ::: "memory")
#define CP_WAIT0()   asm volatile("cp.async.wait_group 0;" ::: "memory")

__global__ void caps_zero_kernel(float* out, int n) {
    int i = blockIdx.x * blockDim.x + threadIdx.x;
    if (i < n) out[i] = 0.0f;
}

__global__ __launch_bounds__(NTHR_, 3)   // 68-reg cap -> 3 CTAs/SM, 30 warps
void caps_main_kernel(const float* __restrict__ x,
                      const float* __restrict__ w,
                      float* __restrict__ out)
{
    // Double-buffered per-ic weights (2 x 1280 floats = 10 KB) + alpha exchange
    __shared__ __align__(16) float sw[2][WPC_];
    __shared__ float salpha[OC_][16];

    const int tid   = threadIdx.x;
    const int c     = tid >> 5;          // warp -> output capsule
    const int lane  = tid & 31;
    const int h     = lane & 1;          // e-half: e in [8h, 8h+8)
    const int blo   = lane >> 1;         // 0..15
    const int ig    = blockIdx.x >> 1;   // ic-group
    const int bhalf = blockIdx.x & 1;
    const int b     = bhalf * 16 + blo;  // batch index
    const int i0    = ig * GI_;

    ull oacc2[EP_];
    #pragma unroll
    for (int k = 0; k < EP_; k++) oacc2[k] = 0ULL;

    // ---- Prologue: stage ic0 weights (cp.async; 320 x 16B = 1280 floats) ----
    {
        const float4* wg = reinterpret_cast<const float4*>(w + (size_t)i0 * WPC_);
        CP16(smaddr(&sw[0][0]) + tid * 16, wg + tid);
        CP_COMMIT();
    }
    CP_WAIT0();
    __syncthreads();

    int pb = 0;
    for (int ii = 0; ii < GI_; ii++) {
        // ---- Stage next ic weights into the other buffer ----
        if (ii + 1 < GI_) {
            const float4* wg = reinterpret_cast<const float4*>(
                w + (size_t)(i0 + ii + 1) * WPC_);
            CP16(smaddr(&sw[pb ^ 1][0]) + tid * 16, wg + tid);
            CP_COMMIT();
        }

        // x row, UNNORMALIZED (scale cancels exactly through the final h and
        // alpha normalizations). Loaded directly (all 10 warps in this CTA
        // read the same rows -> L1-hot); no prefetch registers held.
        float xr[ID_];
        {
            const float4* xp = reinterpret_cast<const float4*>(
                x + ((size_t)b * IC_ + (i0 + ii)) * ID_);
            float4 xa = xp[0], xb = xp[1];
            xr[0] = xa.x; xr[1] = xa.y; xr[2] = xa.z; xr[3] = xa.w;
            xr[4] = xb.x; xr[5] = xb.y; xr[6] = xb.z; xr[7] = xb.w;
        }

        // This thread's weight slice base: w[i, c, d, 8h..8h+8).
        // Streamed from smem (2 distinct addresses per warp per load ->
        // broadcast, conflict-free).
        const ulonglong2* wq = reinterpret_cast<const ulonglong2*>(
            sw[pb] + c * (ID_ * OD_) + h * EH_);

        // ---- NNMF (multiplicative update, renorm deferred), e-split x2 ----
        //   s_d     = sum_e cur[e]*w[d,e]   (half-dot + shfl with partner)
        //   cur[e] *= sum_d x[d]*w[d,e] / (s_d + EPS)
        ull cur2[EP_];
        #pragma unroll
        for (int k = 0; k < EP_; k++)
            cur2[k] = 0x3D8000003D800000ULL;  // (1/16, 1/16)

        for (int it = 0; it < N_ITER_; it++) {
            // Phase 1: 8 independent half-dots (2-deep FMA2 chains)
            float t[ID_];
            #pragma unroll
            for (int d = 0; d < ID_; d++) {
                ulonglong2 v0 = wq[d * 4 + 0];
                ulonglong2 v1 = wq[d * 4 + 1];
                ull sa = MUL2(cur2[0], v0.x);
                ull sb = MUL2(cur2[1], v0.y);
                sa = FMA2(cur2[2], v1.x, sa);
                sb = FMA2(cur2[3], v1.y, sb);
                t[d] = SUM2(ADD2(sa, sb));
            }
            // Phase 2: batched shfls (latencies pipeline across d), then rcps
            #pragma unroll
            for (int d = 0; d < ID_; d++)
                t[d] = t[d] + __shfl_xor_sync(0xffffffffu, t[d], 1);
            #pragma unroll
            for (int d = 0; d < ID_; d++)
                t[d] = xr[d] * frcp(t[d] + EPS_);
            // Phase 3: acc[e] = sum_d w[d,e]*t[d]  (single bank, 8-deep; the
            // 30-warp occupancy hides the chain)
            ull acc2[EP_];
            {
                ull t2 = PACK2(t[0], t[0]);
                ulonglong2 v0 = wq[0];
                ulonglong2 v1 = wq[1];
                acc2[0] = MUL2(v0.x, t2); acc2[1] = MUL2(v0.y, t2);
                acc2[2] = MUL2(v1.x, t2); acc2[3] = MUL2(v1.y, t2);
            }
            #pragma unroll
            for (int d = 1; d < ID_; d++) {
                ull t2 = PACK2(t[d], t[d]);
                ulonglong2 v0 = wq[d * 4 + 0];
                ulonglong2 v1 = wq[d * 4 + 1];
                acc2[0] = FMA2(v0.x, t2, acc2[0]);
                acc2[1] = FMA2(v0.y, t2, acc2[1]);
                acc2[2] = FMA2(v1.x, t2, acc2[2]);
                acc2[3] = FMA2(v1.y, t2, acc2[3]);
            }
            #pragma unroll
            for (int k = 0; k < EP_; k++) cur2[k] = MUL2(cur2[k], acc2[k]);
        }

        // ---- h normalization factor (lazy, full sum via shfl) ----
        float hp = SUM2(ADD2(ADD2(cur2[0], cur2[1]), ADD2(cur2[2], cur2[3])));
        float hs = hp + __shfl_xor_sync(0xffffffffu, hp, 1);
        float hr = frcp(hs + EPS_);

        // ---- alpha = hr * sum_d x[d] * (cur . w[d,:]) ----
        float A = 0.0f;
        #pragma unroll
        for (int d = 0; d < ID_; d++) {
            ulonglong2 v0 = wq[d * 4 + 0];
            ulonglong2 v1 = wq[d * 4 + 1];
            ull sa = MUL2(cur2[0], v0.x);
            ull sb = MUL2(cur2[1], v0.y);
            sa = FMA2(cur2[2], v1.x, sa);
            sb = FMA2(cur2[3], v1.y, sb);
            A = fmaf(xr[d], SUM2(ADD2(sa, sb)), A);
        }
        A = A + __shfl_xor_sync(0xffffffffu, A, 1);   // full-e dot
        float alpha = hr * A;

        salpha[c][blo] = alpha;   // both halves write the identical value
        __syncthreads();

        float asum = 0.0f;
        #pragma unroll
        for (int cc = 0; cc < OC_; cc++) asum += salpha[cc][blo];
        float sc = hr * alpha * frcp(asum + EPS_);    // h-scale * alpha_n
        ull sc2 = PACK2(sc, sc);
        #pragma unroll
        for (int k = 0; k < EP_; k++) oacc2[k] = FMA2(cur2[k], sc2, oacc2[k]);

        // ---- Rotate buffers ----
        if (ii + 1 < GI_) {
            CP_WAIT0();
            __syncthreads();   // staged weights visible; salpha reads done
            pb ^= 1;
        }
    }

    // ---- Accumulate this CTA's contribution into out[b, c, 8h..8h+8) ----
    float* op = out + ((size_t)b * OC_ + c) * OD_ + h * EH_;
    #pragma unroll
    for (int k = 0; k < EP_; k++) {
        atomicAdd(op + 2 * k + 0, LO2(oacc2[k]));
        atomicAdd(op + 2 * k + 1, HI2(oacc2[k]));
    }
}

extern "C" void kernel_launch(void* const* d_in, const int* in_sizes, int n_in,
                              void* d_out, int out_size)
{
    const float* x = (const float*)d_in[0];
    const float* w = (const float*)d_in[1];
    // Defensive: identify tensors by size (x = 294912, w = 1474560).
    if (n_in >= 2 && in_sizes[0] == IC_ * OC_ * ID_ * OD_) {
        const float* t = x; x = w; w = t;
    }
    float* out = (float*)d_out;

    caps_zero_kernel<<<(out_size + 255) / 256, 256>>>(out, out_size);
    caps_main_kernel<<<NBLK_, NTHR_>>>(x, w, out);
}